// round 9
// baseline (speedup 1.0000x reference)
#include <cuda_runtime.h>

// StepRelu: y = 0 for x<=0; ((ceil(x/theta)-1)*theta) for 0<x<=theta*steps; x otherwise.
// theta = 0.1, steps = 16 -> upper = 1.6.
// R9: persistent grid-stride variant of the R5 roofline config.
// One wave: 1184 CTAs (148 SM x 8 resident), VEC=4 float4/thread,
// streaming hints. Removes ~27 wave transitions + per-wave tail straggle.

#define VEC 4
#define NTHREADS 256
#define NBLOCKS 1184   // 148 SMs x 8 CTAs (31 regs x 256 thr x 8 = full RF)

__device__ __forceinline__ float step_relu(float x) {
    const float theta     = 0.1f;
    const float inv_theta = 10.0f;
    const float upper     = 1.6f;
    float binned = (ceilf(x * inv_theta) - 1.0f) * theta;
    float y = (x <= upper) ? binned : x;
    return (x <= 0.0f) ? 0.0f : y;
}

__device__ __forceinline__ float4 step_relu4(float4 v) {
    float4 r;
    r.x = step_relu(v.x);
    r.y = step_relu(v.y);
    r.z = step_relu(v.z);
    r.w = step_relu(v.w);
    return r;
}

// Persistent fast path: n4 must be divisible by NTHREADS*VEC (chunk = 1024).
__global__ void __launch_bounds__(NTHREADS) step_relu_persist(
    const float4* __restrict__ in, float4* __restrict__ out, int n4)
{
    const int chunk = NTHREADS * VEC;            // 1024 float4s per CTA-iteration
    const int stride = chunk * NBLOCKS;
    int base = blockIdx.x * chunk + threadIdx.x;

    for (; base < n4; base += stride) {
        float4 v[VEC];
#pragma unroll
        for (int k = 0; k < VEC; k++)
            v[k] = __ldcs(in + base + k * NTHREADS);   // front-batched MLP=4
#pragma unroll
        for (int k = 0; k < VEC; k++)
            __stcs(out + base + k * NTHREADS, step_relu4(v[k]));
    }
}

// Generic guarded path (covers any n4 remainder region).
__global__ void __launch_bounds__(NTHREADS) step_relu_v4_guard(
    const float4* __restrict__ in, float4* __restrict__ out, int start, int n4)
{
    int i = start + blockIdx.x * blockDim.x + threadIdx.x;
    if (i < n4) __stcs(out + i, step_relu4(__ldcs(in + i)));
}

// Scalar tail for n % 4 != 0.
__global__ void step_relu_tail(
    const float* __restrict__ in, float* __restrict__ out, int start, int n)
{
    int i = start + blockIdx.x * blockDim.x + threadIdx.x;
    if (i < n) out[i] = step_relu(in[i]);
}

extern "C" void kernel_launch(void* const* d_in, const int* in_sizes, int n_in,
                              void* d_out, int out_size)
{
    const float* x = (const float*)d_in[0];
    float* y = (float*)d_out;
    int n = in_sizes[0];

    int n4 = n / 4;
    const int chunk = NTHREADS * VEC;     // 1024
    int n4_main = (n4 / chunk) * chunk;   // largest multiple of 1024

    if (n4_main > 0) {
        step_relu_persist<<<NBLOCKS, NTHREADS>>>(
            (const float4*)x, (float4*)y, n4_main);
    }
    int rem4 = n4 - n4_main;
    if (rem4 > 0) {
        int blocks = (rem4 + NTHREADS - 1) / NTHREADS;
        step_relu_v4_guard<<<blocks, NTHREADS>>>(
            (const float4*)x, (float4*)y, n4_main, n4);
    }
    int rem = n - n4 * 4;
    if (rem > 0) {
        step_relu_tail<<<1, NTHREADS>>>(x, y, n4 * 4, n);
    }
}

// round 10
// speedup vs baseline: 1.2490x; 1.2490x over previous
#include <cuda_runtime.h>

// StepRelu: y = 0 for x<=0; ((ceil(x/theta)-1)*theta) for 0<x<=theta*steps; x otherwise.
// theta = 0.1, steps = 16 -> upper = 1.6.
// FINAL (R5 config): 4x float4 per thread, loads front-batched for MLP,
// streaming cache hints both sides, oversubscribed launch (32768 CTAs) so
// fresh CTAs keep loads in flight. Measured 85-86.6% of HBM spec (6.8-6.9 TB/s).
// Rejected by measurement: VEC=8 (occupancy loss cancels MLP gain),
// __stwt (loses L2 write aggregation), persistent grid-stride (loop-carried
// register reuse collapses MLP; DRAM dropped to 73%).

#define VEC 4  // float4s per thread

__device__ __forceinline__ float step_relu(float x) {
    const float theta     = 0.1f;
    const float inv_theta = 10.0f;
    const float upper     = 1.6f;
    float binned = (ceilf(x * inv_theta) - 1.0f) * theta;
    float y = (x <= upper) ? binned : x;
    return (x <= 0.0f) ? 0.0f : y;
}

__device__ __forceinline__ float4 step_relu4(float4 v) {
    float4 r;
    r.x = step_relu(v.x);
    r.y = step_relu(v.y);
    r.z = step_relu(v.z);
    r.w = step_relu(v.w);
    return r;
}

// Fast path: n4 divisible by blockDim*VEC, no bounds checks.
__global__ void __launch_bounds__(256) step_relu_v4x4_exact(
    const float4* __restrict__ in, float4* __restrict__ out)
{
    int base = blockIdx.x * (256 * VEC) + threadIdx.x;

    float4 v[VEC];
#pragma unroll
    for (int k = 0; k < VEC; k++)
        v[k] = __ldcs(in + base + k * 256);   // independent, front-batched

#pragma unroll
    for (int k = 0; k < VEC; k++)
        __stcs(out + base + k * 256, step_relu4(v[k]));
}

// Generic guarded path (covers any n4 remainder region).
__global__ void __launch_bounds__(256) step_relu_v4_guard(
    const float4* __restrict__ in, float4* __restrict__ out, int start, int n4)
{
    int i = start + blockIdx.x * blockDim.x + threadIdx.x;
    if (i < n4) __stcs(out + i, step_relu4(__ldcs(in + i)));
}

// Scalar tail for n % 4 != 0.
__global__ void step_relu_tail(
    const float* __restrict__ in, float* __restrict__ out, int start, int n)
{
    int i = start + blockIdx.x * blockDim.x + threadIdx.x;
    if (i < n) out[i] = step_relu(in[i]);
}

extern "C" void kernel_launch(void* const* d_in, const int* in_sizes, int n_in,
                              void* d_out, int out_size)
{
    const float* x = (const float*)d_in[0];
    float* y = (float*)d_out;
    int n = in_sizes[0];

    int n4 = n / 4;
    const int per_block = 256 * VEC;          // 1024 float4s per block
    int exact_blocks = n4 / per_block;

    if (exact_blocks > 0) {
        step_relu_v4x4_exact<<<exact_blocks, 256>>>(
            (const float4*)x, (float4*)y);
    }
    int done4 = exact_blocks * per_block;
    int rem4 = n4 - done4;
    if (rem4 > 0) {
        int blocks = (rem4 + 255) / 256;
        step_relu_v4_guard<<<blocks, 256>>>(
            (const float4*)x, (float4*)y, done4, n4);
    }
    int rem = n - n4 * 4;
    if (rem > 0) {
        step_relu_tail<<<1, 256>>>(x, y, n4 * 4, n);
    }
}

// round 12
// speedup vs baseline: 1.2593x; 1.0082x over previous
#include <cuda_runtime.h>

// StepRelu: y = 0 for x<=0; ((ceil(x/theta)-1)*theta) for 0<x<=theta*steps; x otherwise.
// theta = 0.1, steps = 16 -> upper = 1.6.
// R12 (= R11 resubmit after infra failure): R5 roofline config at finer CTA
// granularity (128-thread blocks). Same 31 regs, same MLP=4 front-batched
// LDG.128, same streaming hints; 65536 CTAs halve T_CTA -> less per-wave
// tail straggle (B300 spread model).

#define VEC 4        // float4s per thread
#define NTHREADS 128

__device__ __forceinline__ float step_relu(float x) {
    const float theta     = 0.1f;
    const float inv_theta = 10.0f;
    const float upper     = 1.6f;
    float binned = (ceilf(x * inv_theta) - 1.0f) * theta;
    float y = (x <= upper) ? binned : x;
    return (x <= 0.0f) ? 0.0f : y;
}

__device__ __forceinline__ float4 step_relu4(float4 v) {
    float4 r;
    r.x = step_relu(v.x);
    r.y = step_relu(v.y);
    r.z = step_relu(v.z);
    r.w = step_relu(v.w);
    return r;
}

// Fast path: n4 divisible by NTHREADS*VEC (512), no bounds checks.
__global__ void __launch_bounds__(NTHREADS) step_relu_v4x4_128(
    const float4* __restrict__ in, float4* __restrict__ out)
{
    int base = blockIdx.x * (NTHREADS * VEC) + threadIdx.x;

    float4 v[VEC];
#pragma unroll
    for (int k = 0; k < VEC; k++)
        v[k] = __ldcs(in + base + k * NTHREADS);   // independent, front-batched

#pragma unroll
    for (int k = 0; k < VEC; k++)
        __stcs(out + base + k * NTHREADS, step_relu4(v[k]));
}

// Generic guarded path (covers any n4 remainder region).
__global__ void __launch_bounds__(NTHREADS) step_relu_v4_guard(
    const float4* __restrict__ in, float4* __restrict__ out, int start, int n4)
{
    int i = start + blockIdx.x * blockDim.x + threadIdx.x;
    if (i < n4) __stcs(out + i, step_relu4(__ldcs(in + i)));
}

// Scalar tail for n % 4 != 0.
__global__ void step_relu_tail(
    const float* __restrict__ in, float* __restrict__ out, int start, int n)
{
    int i = start + blockIdx.x * blockDim.x + threadIdx.x;
    if (i < n) out[i] = step_relu(in[i]);
}

extern "C" void kernel_launch(void* const* d_in, const int* in_sizes, int n_in,
                              void* d_out, int out_size)
{
    const float* x = (const float*)d_in[0];
    float* y = (float*)d_out;
    int n = in_sizes[0];

    int n4 = n / 4;
    const int per_block = NTHREADS * VEC;     // 512 float4s per block
    int exact_blocks = n4 / per_block;

    if (exact_blocks > 0) {
        step_relu_v4x4_128<<<exact_blocks, NTHREADS>>>(
            (const float4*)x, (float4*)y);
    }
    int done4 = exact_blocks * per_block;
    int rem4 = n4 - done4;
    if (rem4 > 0) {
        int blocks = (rem4 + NTHREADS - 1) / NTHREADS;
        step_relu_v4_guard<<<blocks, NTHREADS>>>(
            (const float4*)x, (float4*)y, done4, n4);
    }
    int rem = n - n4 * 4;
    if (rem > 0) {
        step_relu_tail<<<1, NTHREADS>>>(x, y, n4 * 4, n);
    }
}